// round 11
// baseline (speedup 1.0000x reference)
#include <cuda_runtime.h>
#include <math_constants.h>

// Problem constants (fixed by the dataset reference)
#define BATCH   8
#define NPTS    16384
#define MPTS    4096
#define CS      256
#define CF      128
#define COUT    (CS + CF)

#define NCH     32                 // radius chunks
#define CL      128                // candidates per chunk (7-bit local idx)

// Scratch (__device__ globals; no allocation)
__device__ float4 g_ct[BATCH * MPTS];        // sorted-by-radius (x,y,z,0.5|y|^2)
__device__ int    g_ci[BATCH * MPTS];        // original candidate index
__device__ int    g_qo[BATCH * NPTS];        // queries grouped by radius bin
__device__ int2   g_top[BATCH * NPTS * 3];   // final {d_bits, idx} per query

// ---------------------------------------------------------------------------
// K1: per-batch bitonic sort of candidates by h = 0.5|y|^2 (== by radius).
// ---------------------------------------------------------------------------
__global__ __launch_bounds__(512)
void sort_cand_kernel(const float* __restrict__ sxyz)
{
    __shared__ float sk[MPTS];
    __shared__ int   sv[MPTS];
    const int b   = blockIdx.x;
    const int tid = threadIdx.x;
    const float* yb = sxyz + (size_t)b * MPTS * 3;

    for (int i = tid; i < MPTS; i += 512) {
        const float y0 = yb[i*3], y1 = yb[i*3+1], y2 = yb[i*3+2];
        sk[i] = 0.5f * (y0*y0 + y1*y1 + y2*y2);
        sv[i] = i;
    }
    __syncthreads();

    for (int k = 2; k <= MPTS; k <<= 1)
        for (int j = k >> 1; j > 0; j >>= 1) {
            for (int i = tid; i < MPTS; i += 512) {
                const int ixj = i ^ j;
                if (ixj > i) {
                    const bool up = ((i & k) == 0);
                    const float a = sk[i], c = sk[ixj];
                    if ((a > c) == up) {
                        sk[i] = c; sk[ixj] = a;
                        const int t = sv[i]; sv[i] = sv[ixj]; sv[ixj] = t;
                    }
                }
            }
            __syncthreads();
        }

    for (int i = tid; i < MPTS; i += 512) {
        const int m = sv[i];
        g_ct[b*MPTS + i] = make_float4(yb[m*3], yb[m*3+1], yb[m*3+2], sk[i]);
        g_ci[b*MPTS + i] = m;
    }
}

// ---------------------------------------------------------------------------
// K2: per-batch grouping of queries into 64 radius bins (order within bin
// arbitrary -- affects only scheduling, not output values).
// ---------------------------------------------------------------------------
__global__ __launch_bounds__(256)
void group_query_kernel(const float* __restrict__ xyz)
{
    __shared__ int cnt[64];
    __shared__ int off[64];
    const int b   = blockIdx.x;
    const int tid = threadIdx.x;
    const float* xb = xyz + (size_t)b * NPTS * 3;

    if (tid < 64) cnt[tid] = 0;
    __syncthreads();

    for (int n = tid; n < NPTS; n += 256) {
        const float x0 = xb[n*3], x1 = xb[n*3+1], x2 = xb[n*3+2];
        const float r  = sqrtf(x0*x0 + x1*x1 + x2*x2);
        const int bin  = min(63, (int)(r * (64.0f / 3.5f)));
        atomicAdd(&cnt[bin], 1);
    }
    __syncthreads();
    if (tid == 0) {
        int s = 0;
        for (int i = 0; i < 64; i++) { off[i] = s; s += cnt[i]; }
    }
    __syncthreads();
    for (int n = tid; n < NPTS; n += 256) {
        const float x0 = xb[n*3], x1 = xb[n*3+1], x2 = xb[n*3+2];
        const float r  = sqrtf(x0*x0 + x1*x1 + x2*x2);
        const int bin  = min(63, (int)(r * (64.0f / 3.5f)));
        const int p    = atomicAdd(&off[bin], 1);
        g_qo[b*NPTS + p] = n;
    }
}

// ---------------------------------------------------------------------------
// K3: exact 3-NN via radius-banded chunk walk. Thread per query.
// Grid 512 CTAs x 256 thr (64 CTAs per batch).
// ---------------------------------------------------------------------------
__global__ __launch_bounds__(256)
void knn_kernel(const float* __restrict__ xyz)
{
    __shared__ float rb[NCH + 1];    // chunk lower-boundary radii
    const int bid  = blockIdx.x;
    const int b    = bid >> 6;
    const int tile = bid & 63;
    const int tid  = threadIdx.x;
    const float4* ct = g_ct + b * MPTS;

    if (tid < NCH) rb[tid] = sqrtf(2.0f * ct[tid * CL].w);
    if (tid == 0)  rb[NCH] = CUDART_INF_F;
    __syncthreads();

    const int rank = tile * 256 + tid;
    const int n    = g_qo[b*NPTS + rank];
    const float* xq = xyz + ((size_t)b * NPTS + n) * 3;
    const float x0 = xq[0], x1 = xq[1], x2 = xq[2];
    const float nx = -x0, ny = -x1, nz = -x2;
    const float hx = 0.5f * (x0*x0 + x1*x1 + x2*x2);
    const float rx = sqrtf(2.0f * hx);

    // largest c in [0,31] with rb[c] <= rx
    int c0 = 0;
    #pragma unroll
    for (int s = 16; s > 0; s >>= 1) {
        const int t = c0 + s;
        if (t < NCH && rb[t] <= rx) c0 = t;
    }

    float D0 = CUDART_INF_F, D1 = CUDART_INF_F, D2 = CUDART_INF_F;
    int   I0 = 0, I1 = 0, I2 = 0;
    int hi = c0, lo = c0 - 1;

    while (true) {
        // exact side bounds: d >= (rx - ry)^2
        const float dhi = (hi < NCH) ? fmaxf(rb[hi] - rx, 0.0f) : CUDART_INF_F;
        const float dlo = (lo >= 0)  ? fmaxf(rx - rb[lo + 1], 0.0f) : CUDART_INF_F;
        const bool ahi = (hi < NCH) && (dhi * dhi < D2);
        const bool alo = (lo >= 0)  && (dlo * dlo < D2);
        const bool any = ahi || alo;
        if (!__any_sync(0xFFFFFFFFu, any)) break;

        const bool side_hi = ahi && (!alo || dhi <= dlo);
        const int  c = any ? (side_hi ? hi : lo) : c0;   // idle lanes: harmless addr

        // scan chunk c: branch-free top-3 float keys (16 mantissa | 7-bit j)
        float k0 = CUDART_INF_F, k1 = CUDART_INF_F, k2 = CUDART_INF_F;
        const float4* base = ct + c * CL;
        #pragma unroll 4
        for (int j = 0; j < CL; j++) {
            const float4 y = __ldg(&base[j]);
            // s = 0.5|y|^2 - x.y  (monotone in d; sign handled by float min/max)
            const float s = fmaf(y.x, nx, fmaf(y.y, ny, fmaf(y.z, nz, y.w)));
            const float key = __int_as_float((__float_as_int(s) & ~(CL - 1)) | j);
            const float M0 = fmaxf(k0, key);  k0 = fminf(k0, key);
            const float M1 = fmaxf(k1, M0);   k1 = fminf(k1, M0);
            k2 = fminf(k2, M1);
        }

        if (any) {
            // merge 3 chunk winners with exact distances
            const float kk[3] = {k0, k1, k2};
            #pragma unroll
            for (int r = 0; r < 3; r++) {
                const int jloc = __float_as_int(kk[r]) & (CL - 1);
                const int gs   = c * CL + jloc;
                const float4 y = __ldg(&ct[gs]);
                const float s  = fmaf(y.x, nx, fmaf(y.y, ny, fmaf(y.z, nz, y.w)));
                const float d  = 2.0f * (hx + s);
                const int   gi = g_ci[b*MPTS + gs];
                if (d < D2) {
                    if (d < D1) {
                        D2 = D1; I2 = I1;
                        if (d < D0) { D1 = D0; I1 = I0; D0 = d; I0 = gi; }
                        else        { D1 = d;  I1 = gi; }
                    } else { D2 = d; I2 = gi; }
                }
            }
            if (side_hi) hi++; else lo--;
        }
    }

    const size_t o = ((size_t)b * NPTS + n) * 3;
    g_top[o + 0] = make_int2(__float_as_int(D0), I0);
    g_top[o + 1] = make_int2(__float_as_int(D1), I1);
    g_top[o + 2] = make_int2(__float_as_int(D2), I2);
}

// ---------------------------------------------------------------------------
// K4: warp-per-query weights + gather + interp + concat. Grid (2048, 8).
// ---------------------------------------------------------------------------
__global__ __launch_bounds__(256)
void interp_kernel(const float* __restrict__ feat,
                   const float* __restrict__ sfeat,
                   float* __restrict__ out)
{
    const int b    = blockIdx.y;
    const int warp = threadIdx.x >> 5;
    const int lane = threadIdx.x & 31;
    const int n    = blockIdx.x * 8 + warp;

    int2 t = make_int2(0, 0);
    if (lane < 3) t = g_top[((size_t)b * NPTS + n) * 3 + lane];

    float dd[3]; int ii[3];
    #pragma unroll
    for (int r = 0; r < 3; r++) {
        dd[r] = __int_as_float(__shfl_sync(0xFFFFFFFFu, t.x, r));
        ii[r] = __shfl_sync(0xFFFFFFFFu, t.y, r);
    }

    float d0 = fmaxf(dd[0], 1e-10f);
    float d1 = fmaxf(dd[1], 1e-10f);
    float d2 = fmaxf(dd[2], 1e-10f);
    float w0 = 1.0f / (d0 * d0 + 1e-7f);
    float w1 = 1.0f / (d1 * d1 + 1e-7f);
    float w2 = 1.0f / (d2 * d2 + 1e-7f);
    const float inv = 1.0f / (w0 + w1 + w2 + 1e-10f);
    w0 *= inv; w1 *= inv; w2 *= inv;

    const float4* sfb = (const float4*)(sfeat + (size_t)b * MPTS * CS);
    const float4* fb  = (const float4*)(feat  + (size_t)b * NPTS * CF);
    float4*       ob  = (float4*)(out + (size_t)b * NPTS * COUT);

    const float4* r0 = sfb + (size_t)ii[0] * (CS / 4);
    const float4* r1 = sfb + (size_t)ii[1] * (CS / 4);
    const float4* r2 = sfb + (size_t)ii[2] * (CS / 4);
    float4* o = ob + (size_t)n * (COUT / 4);

    #pragma unroll
    for (int c = lane; c < CS / 4; c += 32) {
        const float4 a = r0[c];
        const float4 d = r1[c];
        const float4 e = r2[c];
        float4 rv;
        rv.x = w0 * a.x + w1 * d.x + w2 * e.x;
        rv.y = w0 * a.y + w1 * d.y + w2 * e.y;
        rv.z = w0 * a.z + w1 * d.z + w2 * e.z;
        rv.w = w0 * a.w + w1 * d.w + w2 * e.w;
        o[c] = rv;
    }
    const float4* f = fb + (size_t)n * (CF / 4);
    o[CS / 4 + lane] = f[lane];
}

extern "C" void kernel_launch(void* const* d_in, const int* in_sizes, int n_in,
                              void* d_out, int out_size)
{
    const float* xyz   = (const float*)d_in[0];
    const float* sxyz  = (const float*)d_in[1];
    const float* feat  = (const float*)d_in[2];
    const float* sfeat = (const float*)d_in[3];
    float* out = (float*)d_out;

    sort_cand_kernel<<<BATCH, 512>>>(sxyz);
    group_query_kernel<<<BATCH, 256>>>(xyz);
    knn_kernel<<<BATCH * 64, 256>>>(xyz);
    dim3 g4(NPTS / 8, BATCH);
    interp_kernel<<<g4, 256>>>(feat, sfeat, out);
}

// round 12
// speedup vs baseline: 2.0026x; 2.0026x over previous
#include <cuda_runtime.h>
#include <math_constants.h>

// Problem constants (fixed by the dataset reference)
#define BATCH   8
#define NPTS    16384
#define MPTS    4096
#define CS      256
#define CF      128
#define COUT    (CS + CF)

// 4x4x4 spatial grid
#define NC_D    4
#define NCELLS  64
#define GRANGE  3.3f
#define GINV    (NC_D / (2.0f * GRANGE))

// Scratch (__device__ globals; no allocation)
__device__ float4 g_ct[BATCH * MPTS];            // cell-grouped (x,y,z,0.5|y|^2)
__device__ int    g_ci[BATCH * MPTS];            // original candidate index
__device__ int    g_cs[BATCH * (NCELLS + 1)];    // cell start offsets
__device__ float  g_bb[BATCH * NCELLS * 6];      // cell bbox lo3/hi3
__device__ int    g_qo[BATCH * NPTS];            // queries grouped by cell
__device__ int2   g_top[BATCH * NPTS * 3];       // {d_bits, orig idx} per query

__device__ __forceinline__ int cell_of(float x, float y, float z)
{
    const int cx = min(NC_D - 1, max(0, (int)((x + GRANGE) * GINV)));
    const int cy = min(NC_D - 1, max(0, (int)((y + GRANGE) * GINV)));
    const int cz = min(NC_D - 1, max(0, (int)((z + GRANGE) * GINV)));
    return (cz * NC_D + cy) * NC_D + cx;
}

// order-preserving float<->uint for atomic min/max
__device__ __forceinline__ unsigned encf(float f) {
    const unsigned u = __float_as_uint(f);
    return (u & 0x80000000u) ? ~u : (u | 0x80000000u);
}
__device__ __forceinline__ float decf(unsigned e) {
    const unsigned u = (e & 0x80000000u) ? (e & 0x7FFFFFFFu) : ~e;
    return __uint_as_float(u);
}

// ---------------------------------------------------------------------------
// K1: group candidates by cell, compute per-cell data bbox. 1 CTA per batch.
// ---------------------------------------------------------------------------
__global__ __launch_bounds__(256)
void cand_group_kernel(const float* __restrict__ sxyz)
{
    __shared__ int cnt[NCELLS];
    __shared__ int off[NCELLS];
    __shared__ unsigned loE[NCELLS * 3], hiE[NCELLS * 3];
    const int b = blockIdx.x, tid = threadIdx.x;
    const float* yb = sxyz + (size_t)b * MPTS * 3;

    if (tid < NCELLS) cnt[tid] = 0;
    for (int i = tid; i < NCELLS * 3; i += 256) { loE[i] = 0xFFFFFFFFu; hiE[i] = 0u; }
    __syncthreads();

    for (int i = tid; i < MPTS; i += 256)
        atomicAdd(&cnt[cell_of(yb[i*3], yb[i*3+1], yb[i*3+2])], 1);
    __syncthreads();

    if (tid == 0) {
        int s = 0;
        for (int c = 0; c < NCELLS; c++) {
            off[c] = s; g_cs[b * (NCELLS + 1) + c] = s; s += cnt[c];
        }
        g_cs[b * (NCELLS + 1) + NCELLS] = s;
    }
    __syncthreads();

    for (int i = tid; i < MPTS; i += 256) {
        const float y0 = yb[i*3], y1 = yb[i*3+1], y2 = yb[i*3+2];
        const int c = cell_of(y0, y1, y2);
        const int p = atomicAdd(&off[c], 1);
        g_ct[b * MPTS + p] = make_float4(y0, y1, y2, 0.5f * (y0*y0 + y1*y1 + y2*y2));
        g_ci[b * MPTS + p] = i;
        atomicMin(&loE[c*3+0], encf(y0)); atomicMax(&hiE[c*3+0], encf(y0));
        atomicMin(&loE[c*3+1], encf(y1)); atomicMax(&hiE[c*3+1], encf(y1));
        atomicMin(&loE[c*3+2], encf(y2)); atomicMax(&hiE[c*3+2], encf(y2));
    }
    __syncthreads();

    for (int c = tid; c < NCELLS; c += 256) {
        g_bb[(b*NCELLS + c)*6 + 0] = decf(loE[c*3+0]);
        g_bb[(b*NCELLS + c)*6 + 1] = decf(loE[c*3+1]);
        g_bb[(b*NCELLS + c)*6 + 2] = decf(loE[c*3+2]);
        g_bb[(b*NCELLS + c)*6 + 3] = decf(hiE[c*3+0]);
        g_bb[(b*NCELLS + c)*6 + 4] = decf(hiE[c*3+1]);
        g_bb[(b*NCELLS + c)*6 + 5] = decf(hiE[c*3+2]);
    }
}

// ---------------------------------------------------------------------------
// K2: group queries by cell (order within cell arbitrary). 1 CTA per batch.
// ---------------------------------------------------------------------------
__global__ __launch_bounds__(256)
void query_group_kernel(const float* __restrict__ xyz)
{
    __shared__ int cnt[NCELLS];
    __shared__ int off[NCELLS];
    const int b = blockIdx.x, tid = threadIdx.x;
    const float* xb = xyz + (size_t)b * NPTS * 3;

    if (tid < NCELLS) cnt[tid] = 0;
    __syncthreads();
    for (int n = tid; n < NPTS; n += 256)
        atomicAdd(&cnt[cell_of(xb[n*3], xb[n*3+1], xb[n*3+2])], 1);
    __syncthreads();
    if (tid == 0) {
        int s = 0;
        for (int c = 0; c < NCELLS; c++) { off[c] = s; s += cnt[c]; }
    }
    __syncthreads();
    for (int n = tid; n < NPTS; n += 256) {
        const int c = cell_of(xb[n*3], xb[n*3+1], xb[n*3+2]);
        g_qo[b * NPTS + atomicAdd(&off[c], 1)] = n;
    }
}

// ---------------------------------------------------------------------------
// K3: exact 3-NN with nearest-first cell visits + warp-voted bbox pruning.
// Grid (64, BATCH) x 256 threads; all candidates in 64KB dynamic smem.
// ---------------------------------------------------------------------------
#define KNN_SMEM 69632

__global__ __launch_bounds__(256)
void knn_kernel(const float* __restrict__ xyz)
{
    extern __shared__ char smem[];
    float4* sc     = (float4*)smem;                          // [MPTS]
    float*  bb     = (float*)(smem + MPTS * 16);             // [NCELLS*6]
    int*    cstart = (int*)(smem + MPTS * 16 + 1536);        // [NCELLS+1]
    int*    order  = cstart + 72;                            // [NCELLS]
    float*  skey   = (float*)(order + NCELLS);               // [NCELLS]
    float*  ref    = skey + NCELLS;                          // [3]

    const int b   = blockIdx.y;
    const int tid = threadIdx.x;

    // stage candidates + metadata
    for (int i = tid; i < MPTS; i += 256) sc[i] = g_ct[b * MPTS + i];
    for (int i = tid; i < NCELLS * 6; i += 256) bb[i] = g_bb[b * NCELLS * 6 + i];
    if (tid <= NCELLS) cstart[tid] = g_cs[b * (NCELLS + 1) + tid];

    // this thread's query
    const int n = g_qo[b * NPTS + blockIdx.x * 256 + tid];
    const float* xq = xyz + ((size_t)b * NPTS + n) * 3;
    const float x0 = xq[0], x1 = xq[1], x2 = xq[2];
    const float nx = -x0, ny = -x1, nz = -x2;
    const float xn2 = x0*x0 + x1*x1 + x2*x2;

    if (tid == 0) { ref[0] = x0; ref[1] = x1; ref[2] = x2; }
    __syncthreads();

    // order cells by bbox distance from reference query (empty cells last)
    if (tid < NCELLS) {
        float k;
        if (cstart[tid] == cstart[tid + 1]) k = CUDART_INF_F;
        else {
            const float* B = &bb[tid * 6];
            const float t0 = fmaxf(fmaxf(B[0]-ref[0], ref[0]-B[3]), 0.0f);
            const float t1 = fmaxf(fmaxf(B[1]-ref[1], ref[1]-B[4]), 0.0f);
            const float t2 = fmaxf(fmaxf(B[2]-ref[2], ref[2]-B[5]), 0.0f);
            k = fmaf(t0, t0, fmaf(t1, t1, t2 * t2));
        }
        skey[tid] = k;
        order[tid] = tid;
    }
    __syncthreads();
    for (int k = 2; k <= NCELLS; k <<= 1)
        for (int j = k >> 1; j > 0; j >>= 1) {
            if (tid < NCELLS) {
                const int ixj = tid ^ j;
                if (ixj > tid) {
                    const bool up = ((tid & k) == 0);
                    if ((skey[tid] > skey[ixj]) == up) {
                        const float tk = skey[tid]; skey[tid] = skey[ixj]; skey[ixj] = tk;
                        const int tv = order[tid]; order[tid] = order[ixj]; order[ixj] = tv;
                    }
                }
            }
            __syncthreads();
        }

    // scan: s = 0.5|y|^2 - x.y (monotone in d); d = 2s + |x|^2
    float S0 = CUDART_INF_F, S1 = CUDART_INF_F, S2 = CUDART_INF_F;
    int   I0 = 0, I1 = 0, I2 = 0;

    for (int oi = 0; oi < NCELLS; oi++) {
        const int c   = order[oi];
        const int beg = cstart[c], end = cstart[c + 1];
        if (beg == end) continue;

        const float D2 = fmaf(2.0f, S2, xn2);    // current threshold (inf-safe)
        const float* B = &bb[c * 6];
        const float t0 = fmaxf(fmaxf(B[0]-x0, x0-B[3]), 0.0f);
        const float t1 = fmaxf(fmaxf(B[1]-x1, x1-B[4]), 0.0f);
        const float t2 = fmaxf(fmaxf(B[2]-x2, x2-B[5]), 0.0f);
        const float db = fmaf(t0, t0, fmaf(t1, t1, t2 * t2));

        if (!__any_sync(0xFFFFFFFFu, db < D2)) continue;

        #pragma unroll 4
        for (int j = beg; j < end; j++) {
            const float4 y = sc[j];               // broadcast LDS.128
            const float s = fmaf(y.x, nx, fmaf(y.y, ny, fmaf(y.z, nz, y.w)));
            if (s < S2) {                         // rare after first cells
                if (s < S1) {
                    S2 = S1; I2 = I1;
                    if (s < S0) { S1 = S0; I1 = I0; S0 = s; I0 = j; }
                    else        { S1 = s;  I1 = j; }
                } else { S2 = s; I2 = j; }
            }
        }
    }

    const size_t o = ((size_t)b * NPTS + n) * 3;
    g_top[o + 0] = make_int2(__float_as_int(fmaf(2.0f, S0, xn2)), g_ci[b*MPTS + I0]);
    g_top[o + 1] = make_int2(__float_as_int(fmaf(2.0f, S1, xn2)), g_ci[b*MPTS + I1]);
    g_top[o + 2] = make_int2(__float_as_int(fmaf(2.0f, S2, xn2)), g_ci[b*MPTS + I2]);
}

// ---------------------------------------------------------------------------
// K4: warp-per-query weights + gather + interp + concat. Grid (2048, 8).
// ---------------------------------------------------------------------------
__global__ __launch_bounds__(256)
void interp_kernel(const float* __restrict__ feat,
                   const float* __restrict__ sfeat,
                   float* __restrict__ out)
{
    const int b    = blockIdx.y;
    const int warp = threadIdx.x >> 5;
    const int lane = threadIdx.x & 31;
    const int n    = blockIdx.x * 8 + warp;

    int2 t = make_int2(0, 0);
    if (lane < 3) t = g_top[((size_t)b * NPTS + n) * 3 + lane];

    float dd[3]; int ii[3];
    #pragma unroll
    for (int r = 0; r < 3; r++) {
        dd[r] = __int_as_float(__shfl_sync(0xFFFFFFFFu, t.x, r));
        ii[r] = __shfl_sync(0xFFFFFFFFu, t.y, r);
    }

    float d0 = fmaxf(dd[0], 1e-10f);
    float d1 = fmaxf(dd[1], 1e-10f);
    float d2 = fmaxf(dd[2], 1e-10f);
    float w0 = 1.0f / (d0 * d0 + 1e-7f);
    float w1 = 1.0f / (d1 * d1 + 1e-7f);
    float w2 = 1.0f / (d2 * d2 + 1e-7f);
    const float inv = 1.0f / (w0 + w1 + w2 + 1e-10f);
    w0 *= inv; w1 *= inv; w2 *= inv;

    const float4* sfb = (const float4*)(sfeat + (size_t)b * MPTS * CS);
    const float4* fb  = (const float4*)(feat  + (size_t)b * NPTS * CF);
    float4*       ob  = (float4*)(out + (size_t)b * NPTS * COUT);

    const float4* r0 = sfb + (size_t)ii[0] * (CS / 4);
    const float4* r1 = sfb + (size_t)ii[1] * (CS / 4);
    const float4* r2 = sfb + (size_t)ii[2] * (CS / 4);
    float4* o = ob + (size_t)n * (COUT / 4);

    #pragma unroll
    for (int c = lane; c < CS / 4; c += 32) {
        const float4 a = r0[c];
        const float4 d = r1[c];
        const float4 e = r2[c];
        float4 rv;
        rv.x = w0 * a.x + w1 * d.x + w2 * e.x;
        rv.y = w0 * a.y + w1 * d.y + w2 * e.y;
        rv.z = w0 * a.z + w1 * d.z + w2 * e.z;
        rv.w = w0 * a.w + w1 * d.w + w2 * e.w;
        o[c] = rv;
    }
    const float4* f = fb + (size_t)n * (CF / 4);
    o[CS / 4 + lane] = f[lane];
}

extern "C" void kernel_launch(void* const* d_in, const int* in_sizes, int n_in,
                              void* d_out, int out_size)
{
    const float* xyz   = (const float*)d_in[0];
    const float* sxyz  = (const float*)d_in[1];
    const float* feat  = (const float*)d_in[2];
    const float* sfeat = (const float*)d_in[3];
    float* out = (float*)d_out;

    cudaFuncSetAttribute(knn_kernel,
                         cudaFuncAttributeMaxDynamicSharedMemorySize, KNN_SMEM);

    cand_group_kernel<<<BATCH, 256>>>(sxyz);
    query_group_kernel<<<BATCH, 256>>>(xyz);
    dim3 g3(NPTS / 256, BATCH);
    knn_kernel<<<g3, 256, KNN_SMEM>>>(xyz);
    dim3 g4(NPTS / 8, BATCH);
    interp_kernel<<<g4, 256>>>(feat, sfeat, out);
}